// round 9
// baseline (speedup 1.0000x reference)
#include <cuda_runtime.h>
#include <cuda_fp16.h>
#include <cstdint>

// Problem constants (fixed by the reference)
#define PB   4096          // batch
#define PS   1024          // species / slots
#define PN1  4096          // first-order reactions
#define PN2  16384         // second-order reactions
#define PNT  (PN1 + PN2)   // 20480 total terms
#define NBLK (PNT / PS)    // 20 prepass blocks (1024 terms each)
#define ROWS_PER_BLOCK 4
#define MAIN_THREADS 1024

// ---- static device scratch (no allocations allowed) ----
__device__ int g_blkcnt[NBLK * PS];       // per-(block,slot) term counts
__device__ int g_blkoff[NBLK * PS];       // per-(block,slot) start offsets
__device__ int g_bucket_start[PS + 1];    // CSR over output slots
__device__ __align__(16) uint32_t       g_pair[PNT];  // i0 | i1<<16 (i1==1024 -> *1.0)
__device__ __align__(8)  unsigned short g_pos [PNT];  // unique product-sorted position

// ------------------------------------------------------------------
// P1: per-block slot histograms (NBLK blocks x 1024 threads)
// ------------------------------------------------------------------
__global__ void pre_hist(const int* __restrict__ inds_1p,
                         const int* __restrict__ inds_2p)
{
    __shared__ int cnt[PS];
    int tid = threadIdx.x;
    cnt[tid] = 0;
    __syncthreads();
    int t = blockIdx.x * PS + tid;                  // 0..PNT-1
    int p = (t < PN1) ? inds_1p[t] : inds_2p[t - PN1];
    atomicAdd(&cnt[p], 1);                          // counts are order-independent
    __syncthreads();
    g_blkcnt[blockIdx.x * PS + tid] = cnt[tid];
}

// ------------------------------------------------------------------
// P2: slot totals, exclusive scan, per-(block,slot) offsets
//     (1 block, 1024 threads) — fully deterministic
// ------------------------------------------------------------------
__global__ void pre_scan()
{
    __shared__ int scn[PS];
    int tid = threadIdx.x;
    int total = 0;
    #pragma unroll
    for (int b = 0; b < NBLK; b++) total += g_blkcnt[b * PS + tid];
    scn[tid] = total;
    __syncthreads();
    // Hillis-Steele inclusive scan over slots
    for (int off = 1; off < PS; off <<= 1) {
        int v = (tid >= off) ? scn[tid - off] : 0;
        __syncthreads();
        scn[tid] += v;
        __syncthreads();
    }
    int start = scn[tid] - total;                   // exclusive
    g_bucket_start[tid] = start;
    if (tid == PS - 1) g_bucket_start[PS] = scn[tid];   // == PNT
    // per-block offsets within this slot's bucket (stable block order)
    int run = start;
    #pragma unroll
    for (int b = 0; b < NBLK; b++) {
        g_blkoff[b * PS + tid] = run;
        run += g_blkcnt[b * PS + tid];
    }
}

// ------------------------------------------------------------------
// P3: build term records with DETERMINISTIC stable ranks
//     (NBLK blocks x 1024 threads, term order == thread order)
// ------------------------------------------------------------------
__global__ void pre_build(const int* __restrict__ inds_1r,
                          const int* __restrict__ inds_1p,
                          const int* __restrict__ inds_2r,
                          const int* __restrict__ inds_2p)
{
    __shared__ int cnt[PS];                         // same-slot terms seen in earlier warps
    int tid  = threadIdx.x;
    int wid  = tid >> 5;
    int lane = tid & 31;
    cnt[tid] = 0;
    __syncthreads();

    int t = blockIdx.x * PS + tid;
    int p, i0, i1;
    if (t < PN1) {
        p  = inds_1p[t];
        i0 = inds_1r[t];
        i1 = PS;                                    // sentinel -> ysh[PS] == (1,1,1,1)
    } else {
        int j = t - PN1;
        p  = inds_2p[j];
        i0 = inds_2r[2 * j];
        i1 = inds_2r[2 * j + 1];
    }

    // stable rank among same-slot lanes within this warp (lane order)
    unsigned mask   = __match_any_sync(0xFFFFFFFFu, p);
    int      leader = __ffs(mask) - 1;
    int      rank_w = __popc(mask & ((1u << lane) - 1));
    int      gcount = __popc(mask);

    // warp-serialized accumulation into cnt[] -> deterministic warp order
    int before = 0;
    for (int w = 0; w < PS / 32; w++) {
        if (wid == w) {
            int old = 0;
            if (lane == leader) {                   // one leader per distinct slot
                old = cnt[p];
                cnt[p] = old + gcount;
            }
            before = __shfl_sync(0xFFFFFFFFu, old, leader);
        }
        __syncthreads();
    }

    int pos = g_blkoff[blockIdx.x * PS + p] + before + rank_w;
    g_pair[t] = (uint32_t)i0 | ((uint32_t)i1 << 16);
    g_pos[t]  = (unsigned short)pos;
}

// ------------------------------------------------------------------
// Helper: compute + store one term (4 rows packed as 4 halves)
// ------------------------------------------------------------------
__device__ __forceinline__ void do_term(uint2* __restrict__ vals,
                                        const float4* __restrict__ ysh,
                                        uint32_t pair, int pos,
                                        float r0, float r1, float r2, float r3)
{
    int i0 = pair & 0xFFFFu, i1 = pair >> 16;
    float4 a = ysh[i0];
    float4 b = ysh[i1];
    __half2 lo = __floats2half2_rn(a.x * b.x * r0, a.y * b.y * r1);
    __half2 hi = __floats2half2_rn(a.z * b.z * r2, a.w * b.w * r3);
    uint2 pk;
    pk.x = *reinterpret_cast<uint32_t*>(&lo);
    pk.y = *reinterpret_cast<uint32_t*>(&hi);
    vals[pos] = pk;                                  // STS.64, unique slot
}

// ------------------------------------------------------------------
// Main kernel: 4 batch rows per block, 1024 threads, no atomics.
//   Phase A: 4 terms/iter — one LDG.128 of packed pairs, one LDG.64 of
//            packed positions, 4x LDG.128 coalesced rate loads (4 rows x
//            4 terms), then per-term gather from smem y and one STS.64
//            of 4 packed halves to the unique product-sorted slot.
//   Phase B: per-output-slot contiguous fp32 sum (2-way unrolled,
//            independent accumulator pairs), write 4 rows.
// ------------------------------------------------------------------
__global__ __launch_bounds__(MAIN_THREADS, 1)
void reaction_main(const float* __restrict__ y_in,
                   const float* __restrict__ rate_1,
                   const float* __restrict__ rate_2,
                   float* __restrict__ y_out)
{
    extern __shared__ unsigned char sm[];
    float4* ysh  = (float4*)sm;                        // (PS+1) float4 = 16400 B
    uint2*  vals = (uint2*)(sm + 16512);               // PNT uint2 = 163840 B

    const int tid = threadIdx.x;
    const int b0  = blockIdx.x * ROWS_PER_BLOCK;

    // load four y rows interleaved into smem (each pass coalesced)
    const float* y0 = y_in + (size_t)b0 * PS;
    const float* y1 = y0 + PS;
    const float* y2 = y1 + PS;
    const float* y3 = y2 + PS;
    for (int i = tid; i < PS; i += MAIN_THREADS)
        ysh[i] = make_float4(y0[i], y1[i], y2[i], y3[i]);
    if (tid == 0) ysh[PS] = make_float4(1.0f, 1.0f, 1.0f, 1.0f);
    __syncthreads();

    const float* r1_0 = rate_1 + (size_t)b0 * PN1;
    const float* r1_1 = r1_0 + PN1;
    const float* r1_2 = r1_1 + PN1;
    const float* r1_3 = r1_2 + PN1;
    const float* r2_0 = rate_2 + (size_t)b0 * PN2;
    const float* r2_1 = r2_0 + PN2;
    const float* r2_2 = r2_1 + PN2;
    const float* r2_3 = r2_2 + PN2;

    // Phase A: 4 terms/iter, PNT/4 = 5120, stride 1024 -> 5 iters.
    // Region boundary PN1/4 = 1024 is a multiple of 32 -> warp-uniform branch.
    const uint4* pair4 = (const uint4*)g_pair;         // terms 4q..4q+3
    const uint2* pos4  = (const uint2*)g_pos;          // four packed ushorts
    for (int q = tid; q < PNT / 4; q += MAIN_THREADS) {
        uint4 pr = __ldg(&pair4[q]);
        uint2 pp = __ldg(&pos4[q]);
        int t0 = 4 * q;
        float4 ra0, ra1, ra2, ra3;                     // rows b0..b0+3, terms t0..t0+3
        if (t0 < PN1) {
            ra0 = __ldg((const float4*)(r1_0 + t0));
            ra1 = __ldg((const float4*)(r1_1 + t0));
            ra2 = __ldg((const float4*)(r1_2 + t0));
            ra3 = __ldg((const float4*)(r1_3 + t0));
        } else {
            int u = t0 - PN1;
            ra0 = __ldg((const float4*)(r2_0 + u));
            ra1 = __ldg((const float4*)(r2_1 + u));
            ra2 = __ldg((const float4*)(r2_2 + u));
            ra3 = __ldg((const float4*)(r2_3 + u));
        }
        do_term(vals, ysh, pr.x, (int)(pp.x & 0xFFFFu), ra0.x, ra1.x, ra2.x, ra3.x);
        do_term(vals, ysh, pr.y, (int)(pp.x >> 16),     ra0.y, ra1.y, ra2.y, ra3.y);
        do_term(vals, ysh, pr.z, (int)(pp.y & 0xFFFFu), ra0.z, ra1.z, ra2.z, ra3.z);
        do_term(vals, ysh, pr.w, (int)(pp.y >> 16),     ra0.w, ra1.w, ra2.w, ra3.w);
    }
    __syncthreads();

    // Phase B: per-slot contiguous reduction, 2-way unrolled with
    // independent accumulator pairs (deterministic combine order).
    float* o0 = y_out + (size_t)b0 * PS;
    float* o1 = o0 + PS;
    float* o2 = o1 + PS;
    float* o3 = o2 + PS;
    for (int s = tid; s < PS; s += MAIN_THREADS) {     // exactly one slot per thread
        int st = g_bucket_start[s];
        int en = g_bucket_start[s + 1];
        float a0 = 0.0f, a1 = 0.0f, a2 = 0.0f, a3 = 0.0f;   // even positions
        float c0 = 0.0f, c1 = 0.0f, c2 = 0.0f, c3 = 0.0f;   // odd positions
        int k = st;
        for (; k + 1 < en; k += 2) {
            uint2 pk0 = vals[k];
            uint2 pk1 = vals[k + 1];
            float2 e01 = __half22float2(*reinterpret_cast<__half2*>(&pk0.x));
            float2 e23 = __half22float2(*reinterpret_cast<__half2*>(&pk0.y));
            float2 f01 = __half22float2(*reinterpret_cast<__half2*>(&pk1.x));
            float2 f23 = __half22float2(*reinterpret_cast<__half2*>(&pk1.y));
            a0 += e01.x; a1 += e01.y; a2 += e23.x; a3 += e23.y;
            c0 += f01.x; c1 += f01.y; c2 += f23.x; c3 += f23.y;
        }
        if (k < en) {
            uint2 pk = vals[k];
            float2 e01 = __half22float2(*reinterpret_cast<__half2*>(&pk.x));
            float2 e23 = __half22float2(*reinterpret_cast<__half2*>(&pk.y));
            a0 += e01.x; a1 += e01.y; a2 += e23.x; a3 += e23.y;
        }
        o0[s] = a0 + c0;
        o1[s] = a1 + c1;
        o2[s] = a2 + c2;
        o3[s] = a3 + c3;
    }
}

// ------------------------------------------------------------------
extern "C" void kernel_launch(void* const* d_in, const int* in_sizes, int n_in,
                              void* d_out, int out_size)
{
    const float* y_in    = (const float*)d_in[0];
    const float* rate_1  = (const float*)d_in[1];
    const float* rate_2  = (const float*)d_in[2];
    const int*   inds_1r = (const int*)  d_in[3];
    const int*   inds_1p = (const int*)  d_in[4];
    const int*   inds_2r = (const int*)  d_in[5];
    const int*   inds_2p = (const int*)  d_in[6];
    float*       y_out   = (float*)d_out;

    (void)in_sizes; (void)n_in; (void)out_size;

    const int SMEM = 16512 + PNT * (int)sizeof(uint2);   // 180352 B
    cudaFuncSetAttribute(reaction_main,
                         cudaFuncAttributeMaxDynamicSharedMemorySize, SMEM);

    pre_hist <<<NBLK, PS>>>(inds_1p, inds_2p);
    pre_scan <<<1, PS>>>();
    pre_build<<<NBLK, PS>>>(inds_1r, inds_1p, inds_2r, inds_2p);
    reaction_main<<<PB / ROWS_PER_BLOCK, MAIN_THREADS, SMEM>>>(y_in, rate_1, rate_2, y_out);
}

// round 13
// speedup vs baseline: 1.1312x; 1.1312x over previous
#include <cuda_runtime.h>
#include <cuda_fp16.h>
#include <cstdint>

// Problem constants (fixed by the reference)
#define PB   4096          // batch
#define PS   1024          // species / slots
#define PN1  4096          // first-order reactions
#define PN2  16384         // second-order reactions
#define PNT  (PN1 + PN2)   // 20480 total terms
#define NBLK (PNT / PS)    // 20 prepass blocks (1024 terms each)
#define ROWS_PER_BLOCK 4
#define MAIN_THREADS 1024

// ---- static device scratch (no allocations allowed) ----
__device__ int g_blkcnt[NBLK * PS];       // per-(block,slot) term counts
__device__ int g_blkoff[NBLK * PS];       // per-(block,slot) start offsets
__device__ int g_bucket_start[PS + 1];    // CSR over output slots
__device__ __align__(16) uint32_t       g_pair[PNT];  // i0 | i1<<16 (i1==1024 -> *1.0)
__device__ __align__(8)  unsigned short g_pos [PNT];  // unique product-sorted position

// ------------------------------------------------------------------
// P1: per-block slot histograms (NBLK blocks x 1024 threads)
// ------------------------------------------------------------------
__global__ void pre_hist(const int* __restrict__ inds_1p,
                         const int* __restrict__ inds_2p)
{
    __shared__ int cnt[PS];
    int tid = threadIdx.x;
    cnt[tid] = 0;
    __syncthreads();
    int t = blockIdx.x * PS + tid;                  // 0..PNT-1
    int p = (t < PN1) ? inds_1p[t] : inds_2p[t - PN1];
    atomicAdd(&cnt[p], 1);                          // counts are order-independent
    __syncthreads();
    g_blkcnt[blockIdx.x * PS + tid] = cnt[tid];
}

// ------------------------------------------------------------------
// P2: slot totals, exclusive scan, per-(block,slot) offsets
//     (1 block, 1024 threads) — fully deterministic
// ------------------------------------------------------------------
__global__ void pre_scan()
{
    __shared__ int scn[PS];
    int tid = threadIdx.x;
    int total = 0;
    #pragma unroll
    for (int b = 0; b < NBLK; b++) total += g_blkcnt[b * PS + tid];
    scn[tid] = total;
    __syncthreads();
    // Hillis-Steele inclusive scan over slots
    for (int off = 1; off < PS; off <<= 1) {
        int v = (tid >= off) ? scn[tid - off] : 0;
        __syncthreads();
        scn[tid] += v;
        __syncthreads();
    }
    int start = scn[tid] - total;                   // exclusive
    g_bucket_start[tid] = start;
    if (tid == PS - 1) g_bucket_start[PS] = scn[tid];   // == PNT
    // per-block offsets within this slot's bucket (stable block order)
    int run = start;
    #pragma unroll
    for (int b = 0; b < NBLK; b++) {
        g_blkoff[b * PS + tid] = run;
        run += g_blkcnt[b * PS + tid];
    }
}

// ------------------------------------------------------------------
// P3: build term records with DETERMINISTIC stable ranks
//     (NBLK blocks x 1024 threads, term order == thread order)
// ------------------------------------------------------------------
__global__ void pre_build(const int* __restrict__ inds_1r,
                          const int* __restrict__ inds_1p,
                          const int* __restrict__ inds_2r,
                          const int* __restrict__ inds_2p)
{
    __shared__ int cnt[PS];                         // same-slot terms seen in earlier warps
    int tid  = threadIdx.x;
    int wid  = tid >> 5;
    int lane = tid & 31;
    cnt[tid] = 0;
    __syncthreads();

    int t = blockIdx.x * PS + tid;
    int p, i0, i1;
    if (t < PN1) {
        p  = inds_1p[t];
        i0 = inds_1r[t];
        i1 = PS;                                    // sentinel -> ysh[PS] == ones
    } else {
        int j = t - PN1;
        p  = inds_2p[j];
        i0 = inds_2r[2 * j];
        i1 = inds_2r[2 * j + 1];
    }

    // stable rank among same-slot lanes within this warp (lane order)
    unsigned mask   = __match_any_sync(0xFFFFFFFFu, p);
    int      leader = __ffs(mask) - 1;
    int      rank_w = __popc(mask & ((1u << lane) - 1));
    int      gcount = __popc(mask);

    // warp-serialized accumulation into cnt[] -> deterministic warp order
    int before = 0;
    for (int w = 0; w < PS / 32; w++) {
        if (wid == w) {
            int old = 0;
            if (lane == leader) {                   // one leader per distinct slot
                old = cnt[p];
                cnt[p] = old + gcount;
            }
            before = __shfl_sync(0xFFFFFFFFu, old, leader);
        }
        __syncthreads();
    }

    int pos = g_blkoff[blockIdx.x * PS + p] + before + rank_w;
    g_pair[t] = (uint32_t)i0 | ((uint32_t)i1 << 16);
    g_pos[t]  = (unsigned short)pos;
}

// ------------------------------------------------------------------
// Helper: compute + store one term (4 rows packed as 4 halves).
// y reactants are fp16 in smem (8 B per species); compute in fp32.
// ------------------------------------------------------------------
__device__ __forceinline__ void do_term(uint2* __restrict__ vals,
                                        const uint2* __restrict__ ysh,
                                        uint32_t pair, int pos,
                                        float r0, float r1, float r2, float r3)
{
    int i0 = pair & 0xFFFFu, i1 = pair >> 16;
    uint2 ua = ysh[i0];                              // LDS.64 (was LDS.128)
    uint2 ub = ysh[i1];
    float2 a01 = __half22float2(*reinterpret_cast<__half2*>(&ua.x));
    float2 a23 = __half22float2(*reinterpret_cast<__half2*>(&ua.y));
    float2 b01 = __half22float2(*reinterpret_cast<__half2*>(&ub.x));
    float2 b23 = __half22float2(*reinterpret_cast<__half2*>(&ub.y));
    __half2 lo = __floats2half2_rn(a01.x * b01.x * r0, a01.y * b01.y * r1);
    __half2 hi = __floats2half2_rn(a23.x * b23.x * r2, a23.y * b23.y * r3);
    uint2 pk;
    pk.x = *reinterpret_cast<uint32_t*>(&lo);
    pk.y = *reinterpret_cast<uint32_t*>(&hi);
    vals[pos] = pk;                                  // STS.64, unique slot
}

// ------------------------------------------------------------------
// Main kernel: 4 batch rows per block, 1024 threads, no atomics.
//   Phase A: 4 terms/iter — one LDG.128 of packed pairs, one LDG.64 of
//            packed positions, 4x LDG.128 coalesced rate loads (4 rows x
//            4 terms), two LDS.64 fp16 y-gathers per term, one STS.64
//            of 4 packed halves to the unique product-sorted slot.
//   Phase B: per-output-slot contiguous fp32 sum (2-way unrolled,
//            independent accumulator pairs), write 4 rows.
// ------------------------------------------------------------------
__global__ __launch_bounds__(MAIN_THREADS, 1)
void reaction_main(const float* __restrict__ y_in,
                   const float* __restrict__ rate_1,
                   const float* __restrict__ rate_2,
                   float* __restrict__ y_out)
{
    extern __shared__ unsigned char sm[];
    uint2* ysh  = (uint2*)sm;                          // (PS+1) x 8 B fp16 = 8200 B
    uint2* vals = (uint2*)(sm + 8320);                 // PNT uint2 = 163840 B

    const int tid = threadIdx.x;
    const int b0  = blockIdx.x * ROWS_PER_BLOCK;

    // load four y rows, convert to fp16, interleave into smem
    const float* y0 = y_in + (size_t)b0 * PS;
    const float* y1 = y0 + PS;
    const float* y2 = y1 + PS;
    const float* y3 = y2 + PS;
    for (int i = tid; i < PS; i += MAIN_THREADS) {
        __half2 lo = __floats2half2_rn(y0[i], y1[i]);
        __half2 hi = __floats2half2_rn(y2[i], y3[i]);
        uint2 pk;
        pk.x = *reinterpret_cast<uint32_t*>(&lo);
        pk.y = *reinterpret_cast<uint32_t*>(&hi);
        ysh[i] = pk;
    }
    if (tid == 0) {
        __half2 one2 = __floats2half2_rn(1.0f, 1.0f);
        uint2 pk;
        pk.x = *reinterpret_cast<uint32_t*>(&one2);
        pk.y = pk.x;
        ysh[PS] = pk;                                  // first-order sentinel
    }
    __syncthreads();

    const float* r1_0 = rate_1 + (size_t)b0 * PN1;
    const float* r1_1 = r1_0 + PN1;
    const float* r1_2 = r1_1 + PN1;
    const float* r1_3 = r1_2 + PN1;
    const float* r2_0 = rate_2 + (size_t)b0 * PN2;
    const float* r2_1 = r2_0 + PN2;
    const float* r2_2 = r2_1 + PN2;
    const float* r2_3 = r2_2 + PN2;

    // Phase A: 4 terms/iter, PNT/4 = 5120, stride 1024 -> 5 iters.
    // Region boundary PN1/4 = 1024 is a multiple of 32 -> warp-uniform branch.
    const uint4* pair4 = (const uint4*)g_pair;         // terms 4q..4q+3
    const uint2* pos4  = (const uint2*)g_pos;          // four packed ushorts
    for (int q = tid; q < PNT / 4; q += MAIN_THREADS) {
        uint4 pr = __ldg(&pair4[q]);
        uint2 pp = __ldg(&pos4[q]);
        int t0 = 4 * q;
        float4 ra0, ra1, ra2, ra3;                     // rows b0..b0+3, terms t0..t0+3
        if (t0 < PN1) {
            ra0 = __ldg((const float4*)(r1_0 + t0));
            ra1 = __ldg((const float4*)(r1_1 + t0));
            ra2 = __ldg((const float4*)(r1_2 + t0));
            ra3 = __ldg((const float4*)(r1_3 + t0));
        } else {
            int u = t0 - PN1;
            ra0 = __ldg((const float4*)(r2_0 + u));
            ra1 = __ldg((const float4*)(r2_1 + u));
            ra2 = __ldg((const float4*)(r2_2 + u));
            ra3 = __ldg((const float4*)(r2_3 + u));
        }
        do_term(vals, ysh, pr.x, (int)(pp.x & 0xFFFFu), ra0.x, ra1.x, ra2.x, ra3.x);
        do_term(vals, ysh, pr.y, (int)(pp.x >> 16),     ra0.y, ra1.y, ra2.y, ra3.y);
        do_term(vals, ysh, pr.z, (int)(pp.y & 0xFFFFu), ra0.z, ra1.z, ra2.z, ra3.z);
        do_term(vals, ysh, pr.w, (int)(pp.y >> 16),     ra0.w, ra1.w, ra2.w, ra3.w);
    }
    __syncthreads();

    // Phase B: per-slot contiguous reduction, 2-way unrolled with
    // independent accumulator pairs (deterministic combine order).
    float* o0 = y_out + (size_t)b0 * PS;
    float* o1 = o0 + PS;
    float* o2 = o1 + PS;
    float* o3 = o2 + PS;
    for (int s = tid; s < PS; s += MAIN_THREADS) {     // exactly one slot per thread
        int st = g_bucket_start[s];
        int en = g_bucket_start[s + 1];
        float a0 = 0.0f, a1 = 0.0f, a2 = 0.0f, a3 = 0.0f;   // even positions
        float c0 = 0.0f, c1 = 0.0f, c2 = 0.0f, c3 = 0.0f;   // odd positions
        int k = st;
        for (; k + 1 < en; k += 2) {
            uint2 pk0 = vals[k];
            uint2 pk1 = vals[k + 1];
            float2 e01 = __half22float2(*reinterpret_cast<__half2*>(&pk0.x));
            float2 e23 = __half22float2(*reinterpret_cast<__half2*>(&pk0.y));
            float2 f01 = __half22float2(*reinterpret_cast<__half2*>(&pk1.x));
            float2 f23 = __half22float2(*reinterpret_cast<__half2*>(&pk1.y));
            a0 += e01.x; a1 += e01.y; a2 += e23.x; a3 += e23.y;
            c0 += f01.x; c1 += f01.y; c2 += f23.x; c3 += f23.y;
        }
        if (k < en) {
            uint2 pk = vals[k];
            float2 e01 = __half22float2(*reinterpret_cast<__half2*>(&pk.x));
            float2 e23 = __half22float2(*reinterpret_cast<__half2*>(&pk.y));
            a0 += e01.x; a1 += e01.y; a2 += e23.x; a3 += e23.y;
        }
        o0[s] = a0 + c0;
        o1[s] = a1 + c1;
        o2[s] = a2 + c2;
        o3[s] = a3 + c3;
    }
}

// ------------------------------------------------------------------
extern "C" void kernel_launch(void* const* d_in, const int* in_sizes, int n_in,
                              void* d_out, int out_size)
{
    const float* y_in    = (const float*)d_in[0];
    const float* rate_1  = (const float*)d_in[1];
    const float* rate_2  = (const float*)d_in[2];
    const int*   inds_1r = (const int*)  d_in[3];
    const int*   inds_1p = (const int*)  d_in[4];
    const int*   inds_2r = (const int*)  d_in[5];
    const int*   inds_2p = (const int*)  d_in[6];
    float*       y_out   = (float*)d_out;

    (void)in_sizes; (void)n_in; (void)out_size;

    const int SMEM = 8320 + PNT * (int)sizeof(uint2);    // 172160 B
    cudaFuncSetAttribute(reaction_main,
                         cudaFuncAttributeMaxDynamicSharedMemorySize, SMEM);

    pre_hist <<<NBLK, PS>>>(inds_1p, inds_2p);
    pre_scan <<<1, PS>>>();
    pre_build<<<NBLK, PS>>>(inds_1r, inds_1p, inds_2r, inds_2p);
    reaction_main<<<PB / ROWS_PER_BLOCK, MAIN_THREADS, SMEM>>>(y_in, rate_1, rate_2, y_out);
}